// round 11
// baseline (speedup 1.0000x reference)
#include <cuda_runtime.h>
#include <cuda_fp16.h>
#include <cstdint>

// Problem constants
#define HN 2048   // hidden
#define EN 64     // experts
#define IN 1024   // expert intermediate
#define SIN 4096  // shared intermediate
#define KN 8      // top-k
#define TN 1024   // tokens

// ---------------- scratch (device globals: allocation-free) ----------------
__device__ int    g_cnt[EN];
__device__ int    g_off[EN];
__device__ int    g_list[EN * TN];        // entries: t*KN + k
__device__ float  g_topv[TN * KN];        // sigmoid routing weights
__device__ __half g_xh[TN * HN];          // fp16 copy of x
__device__ __half g_h[TN * KN * IN];      // expert hidden (fp16)   [8192, 1024]
__device__ float  g_moe[TN * KN * HN];    // expert out per pair    [8192, 2048]
__device__ __half g_hs[TN * SIN];         // shared hidden (fp16)   [1024, 4096]
__device__ float  g_sh[TN * HN];          // shared out             [1024, 2048]

// ---------------- helpers ----------------
__device__ __forceinline__ void ldm4(uint32_t r[4], uint32_t a) {
    asm volatile("ldmatrix.sync.aligned.m8n8.x4.shared.b16 {%0,%1,%2,%3}, [%4];"
                 : "=r"(r[0]), "=r"(r[1]), "=r"(r[2]), "=r"(r[3]) : "r"(a));
}

__device__ __forceinline__ void mma16816(float c[4], const uint32_t a[4],
                                         uint32_t b0, uint32_t b1) {
    asm volatile(
        "mma.sync.aligned.m16n8k16.row.col.f32.f16.f16.f32 "
        "{%0,%1,%2,%3},{%4,%5,%6,%7},{%8,%9},{%0,%1,%2,%3};"
        : "+f"(c[0]), "+f"(c[1]), "+f"(c[2]), "+f"(c[3])
        : "r"(a[0]), "r"(a[1]), "r"(a[2]), "r"(a[3]), "r"(b0), "r"(b1));
}

__device__ __forceinline__ uint32_t smem_u32(const void* p) {
    uint32_t a;
    asm("{ .reg .u64 t; cvta.to.shared.u64 t, %1; cvt.u32.u64 %0, t; }" : "=r"(a) : "l"(p));
    return a;
}

__device__ __forceinline__ void sts128(uint32_t addr, uint4 v) {
    asm volatile("st.shared.v4.b32 [%0], {%1,%2,%3,%4};"
                 :: "r"(addr), "r"(v.x), "r"(v.y), "r"(v.z), "r"(v.w) : "memory");
}

__device__ __forceinline__ float4 lds128f(uint32_t a) {
    float4 v;
    asm volatile("ld.shared.v4.f32 {%0,%1,%2,%3}, [%4];"
                 : "=f"(v.x), "=f"(v.y), "=f"(v.z), "=f"(v.w) : "r"(a));
    return v;
}

__device__ __forceinline__ void cpasync16(uint32_t dst, const void* src) {
    asm volatile("cp.async.cg.shared.global [%0], [%1], 16;" :: "r"(dst), "l"(src));
}
#define CP_COMMIT() asm volatile("cp.async.commit_group;" ::: "memory")
#define CP_WAIT1()  asm volatile("cp.async.wait_group 1;" ::: "memory")

__device__ __forceinline__ uint32_t h2u(__half2 h) { return *(uint32_t*)&h; }

__device__ __forceinline__ uint4 f8_to_h8(float4 x, float4 y) {
    return make_uint4(
        h2u(__float22half2_rn(make_float2(x.x, x.y))),
        h2u(__float22half2_rn(make_float2(x.z, x.w))),
        h2u(__float22half2_rn(make_float2(y.x, y.y))),
        h2u(__float22half2_rn(make_float2(y.z, y.w))));
}

// ---------------- init / convert ----------------
__global__ void zero_cnt_kernel() {
    if (threadIdx.x < EN) g_cnt[threadIdx.x] = 0;
}

__global__ void cvt_x_kernel(const float* __restrict__ x) {
    int idx = blockIdx.x * 256 + threadIdx.x;          // TN*HN/4 float4s
    float4 v = *(const float4*)&x[(size_t)idx * 4];
    uint2 o;
    o.x = h2u(__float22half2_rn(make_float2(v.x, v.y)));
    o.y = h2u(__float22half2_rn(make_float2(v.z, v.w)));
    *(uint2*)&g_xh[(size_t)idx * 4] = o;
}

// ---------------- router ----------------
__global__ void router_kernel(const float* __restrict__ x, const float* __restrict__ wg) {
    __shared__ float xs[HN];
    __shared__ float logits[EN];
    int t = blockIdx.x;
    for (int i = threadIdx.x; i < HN; i += blockDim.x) xs[i] = x[(size_t)t * HN + i];
    __syncthreads();
    int warp = threadIdx.x >> 5, lane = threadIdx.x & 31;
    for (int e = warp; e < EN; e += 8) {
        const float* w = wg + (size_t)e * HN;
        float s = 0.f;
        for (int i = lane; i < HN; i += 32) s += xs[i] * w[i];
        #pragma unroll
        for (int o = 16; o; o >>= 1) s += __shfl_xor_sync(0xffffffffu, s, o);
        if (lane == 0) logits[e] = s;
    }
    __syncthreads();
    if (threadIdx.x == 0) {
        #pragma unroll 1
        for (int k = 0; k < KN; k++) {
            int best = 0; float bv = -1e30f;
            for (int e = 0; e < EN; e++) {
                float v = logits[e];
                if (v > bv) { bv = v; best = e; }
            }
            logits[best] = -1e30f;
            g_topv[t * KN + k] = 1.f / (1.f + __expf(-bv));
            int slot = atomicAdd(&g_cnt[best], 1);
            g_list[best * TN + slot] = t * KN + k;
        }
    }
}

__global__ void offsets_kernel() {
    if (threadIdx.x == 0) {
        int s = 0;
        for (int e = 0; e < EN; e++) { g_off[e] = s; s += g_cnt[e]; }
    }
}

// ---------------- fp16 tensor-core GEMM, cp.async pipelined --------------
// C[M,N] = A[M,K] (fp16) * B[N,K]^T (f32 weights, converted in-kernel)
// MODE 0: plain rows.  MODE 1: A row = token (g_list>>3), C row compact.
// MODE 2: A row = compact, C row = g_list entry.
// GUFUSE: B rows interleaved (even=gate, odd=up); epilogue silu(g)*u -> fp16.
// CTA tile 128x256x32, 256 threads, warp grid 2x4 (warp tile 64x64).
// smem rings: A fp16 3x10240 (pitch 80) | Braw f32 3x36864 (pitch 144)
//           | Bcvt fp16 2x20480 (pitch 80).
#define A_SLOT    10240
#define BRAW_SLOT 36864
#define BCVT_SLOT 20480
#define OFF_BRAW  (3 * A_SLOT)                  // 30720
#define OFF_BCVT  (OFF_BRAW + 3 * BRAW_SLOT)    // 141312
#define SMEM_G    (OFF_BCVT + 2 * BCVT_SLOT)    // 182272

template <int MODE, bool GUFUSE>
__global__ void __launch_bounds__(256, 1)
gemm_h(const __half* __restrict__ A, const float* __restrict__ Bw,
       void* __restrict__ Cv, int Kdim, int lda, int ldb, int ldc,
       int Mfixed, long long strideB, int hoff)
{
    extern __shared__ char smem[];
    const int tid = threadIdx.x;
    const int e  = blockIdx.z;
    const int m0 = blockIdx.y * 128;
    const int n0 = blockIdx.x * 256;

    int M = Mfixed;
    const float* Bbase = Bw;
    int off_e = 0;
    if (MODE != 0) {
        M = g_cnt[e];
        if (m0 >= M) return;
        Bbase = Bw + (size_t)e * strideB;
        off_e = g_off[e];
    }

    const uint32_t sbase = smem_u32(smem);

    // ---- A cp.async mapping: row rA = tid>>1, two 16B chunks ----
    const int rA = tid >> 1;
    const int cA = (tid & 1) * 2;
    const __half* pA;
    {
        int gr = m0 + rA;
        int src = (gr < M) ? gr : 0;   // clamp OOB rows (discarded at epilogue)
        if (MODE == 0)      pA = A + (size_t)gr * lda;
        else if (MODE == 1) pA = A + (size_t)(g_list[e * TN + src] >> 3) * lda;
        else                pA = A + (size_t)(off_e + src) * lda;
        pA += cA * 8;
    }
    const uint32_t dA0 = (uint32_t)rA * 80u + (uint32_t)cA * 16u;

    // ---- B cp.async mapping: one row per thread (256 rows) ----
    const float* pB;
    {
        int jg = n0 + tid;
        int brow = GUFUSE ? ((jg & 1) ? (hoff + (jg >> 1)) : (jg >> 1)) : jg;
        pB = Bbase + (size_t)brow * ldb;
    }
    const uint32_t dB = (uint32_t)tid * 144u;

    // ---- ldmatrix offsets (pitch-80 tiles, conflict-free per R4) ----
    const int warp = tid >> 5, lane = tid & 31;
    const int wm = warp & 1, wn = warp >> 1;          // 2 x 4 warp grid
    const int l15 = lane & 15;
    const int lcol = (lane & 16) ? 16 : 0;
    uint32_t aoff[4][2], boff[4][2];
    #pragma unroll
    for (int mf = 0; mf < 4; ++mf) {
        uint32_t r = wm * 64 + mf * 16 + l15;
        #pragma unroll
        for (int ks = 0; ks < 2; ++ks) aoff[mf][ks] = r * 80u + ks * 32u + lcol;
    }
    #pragma unroll
    for (int np = 0; np < 4; ++np) {
        uint32_t r = wn * 64 + np * 16 + l15;
        #pragma unroll
        for (int ks = 0; ks < 2; ++ks) boff[np][ks] = r * 80u + ks * 32u + lcol;
    }

    float acc[4][8][4];
    #pragma unroll
    for (int mf = 0; mf < 4; mf++)
        #pragma unroll
        for (int nf = 0; nf < 8; nf++)
            #pragma unroll
            for (int r = 0; r < 4; r++) acc[mf][nf][r] = 0.f;

    const int nK = Kdim >> 5;

    auto issue_stage = [&](int s) {
        if (s < nK) {
            uint32_t aslot = sbase + (uint32_t)(s % 3) * A_SLOT;
            const __half* as = pA + (s << 5);
            cpasync16(aslot + dA0, as);
            cpasync16(aslot + dA0 + 16, as + 8);
            uint32_t bslot = sbase + OFF_BRAW + (uint32_t)(s % 3) * BRAW_SLOT + dB;
            const float* bs = pB + (s << 5);
            #pragma unroll
            for (int i = 0; i < 8; ++i)
                cpasync16(bslot + i * 16, bs + i * 4);
        }
        CP_COMMIT();
    };
    auto convert_stage = [&](int s) {
        if (s < nK) {
            uint32_t bslot = sbase + OFF_BRAW + (uint32_t)(s % 3) * BRAW_SLOT + dB;
            float4 r[8];
            #pragma unroll
            for (int i = 0; i < 8; ++i) r[i] = lds128f(bslot + i * 16);
            uint32_t bc = sbase + OFF_BCVT + (uint32_t)(s & 1) * BCVT_SLOT
                        + (uint32_t)tid * 80u;
            #pragma unroll
            for (int c = 0; c < 4; ++c)
                sts128(bc + c * 16, f8_to_h8(r[2 * c], r[2 * c + 1]));
        }
    };

    // prologue: stages 0,1 in flight; convert stage 0
    issue_stage(0);
    issue_stage(1);
    CP_WAIT1();          // stage 0 resident (own-thread rows)
    convert_stage(0);
    __syncthreads();     // publish A stage 0 + Bcvt[0]

    for (int kt = 0; kt < nK; ++kt) {
        issue_stage(kt + 2);
        CP_WAIT1();                  // stage kt+1 resident
        convert_stage(kt + 1);       // writes Bcvt[(kt+1)&1] (own rows only)
        const uint32_t abase = sbase + (uint32_t)(kt % 3) * A_SLOT;
        const uint32_t bbase = sbase + OFF_BCVT + (uint32_t)(kt & 1) * BCVT_SLOT;
        #pragma unroll
        for (int ks = 0; ks < 2; ++ks) {
            uint32_t af[4][4], bf[4][4];
            #pragma unroll
            for (int mf = 0; mf < 4; ++mf) ldm4(af[mf], abase + aoff[mf][ks]);
            #pragma unroll
            for (int np = 0; np < 4; ++np) ldm4(bf[np], bbase + boff[np][ks]);
            #pragma unroll
            for (int mf = 0; mf < 4; ++mf)
                #pragma unroll
                for (int nf = 0; nf < 8; ++nf)
                    mma16816(acc[mf][nf], af[mf],
                             bf[nf >> 1][nf & 1], bf[nf >> 1][(nf & 1) | 2]);
        }
        __syncthreads();             // publish next stage's A + Bcvt; guard reuse
    }

    // ---- epilogue ----
    #pragma unroll
    for (int mf = 0; mf < 4; ++mf) {
        #pragma unroll
        for (int half = 0; half < 2; ++half) {
            int rl = wm * 64 + mf * 16 + (lane >> 2) + half * 8;
            int gr = m0 + rl;
            if (gr >= M) continue;
            size_t crow;
            if (MODE == 0)      crow = (size_t)gr;
            else if (MODE == 1) crow = (size_t)(off_e + gr);
            else                crow = (size_t)g_list[e * TN + gr];
            if (GUFUSE) {
                __half* hp = (__half*)Cv + crow * (size_t)hoff
                           + ((n0 + wn * 64) >> 1) + (lane & 3);
                #pragma unroll
                for (int nf = 0; nf < 8; ++nf) {
                    float g = acc[mf][nf][half * 2];
                    float u = acc[mf][nf][half * 2 + 1];
                    float h = g / (1.f + __expf(-g)) * u;
                    hp[nf * 4] = __float2half_rn(h);
                }
            } else {
                float* cp = (float*)Cv + crow * (size_t)ldc + n0 + wn * 64 + (lane & 3) * 2;
                #pragma unroll
                for (int nf = 0; nf < 8; ++nf) {
                    float2 v = make_float2(acc[mf][nf][half * 2], acc[mf][nf][half * 2 + 1]);
                    *(float2*)(cp + nf * 8) = v;
                }
            }
        }
    }
}

// ---------------- combine ----------------
__global__ void combine_kernel(float* __restrict__ out) {
    int idx = blockIdx.x * 256 + threadIdx.x;          // over [1024 * 512] float4
    int t = idx >> 9, d = (idx & 511) * 4;
    float4 acc = make_float4(0.f, 0.f, 0.f, 0.f);
    #pragma unroll
    for (int k = 0; k < KN; k++) {
        float w = g_topv[t * KN + k];
        float4 m = *(const float4*)&g_moe[(size_t)(t * KN + k) * HN + d];
        acc.x += w * m.x; acc.y += w * m.y; acc.z += w * m.z; acc.w += w * m.w;
    }
    float4 s = *(const float4*)&g_sh[(size_t)t * HN + d];
    const float inv = 1.f / (float)(KN + 1);
    float4 o;
    o.x = (s.x + KN * acc.x) * inv;
    o.y = (s.y + KN * acc.y) * inv;
    o.z = (s.z + KN * acc.z) * inv;
    o.w = (s.w + KN * acc.w) * inv;
    *(float4*)&out[(size_t)t * HN + d] = o;
}

// ---------------- launch ----------------
extern "C" void kernel_launch(void* const* d_in, const int* in_sizes, int n_in,
                              void* d_out, int out_size)
{
    const float* x      = (const float*)d_in[0];  // [T,H]
    const float* w_gate = (const float*)d_in[1];  // [E,H]
    const float* w13    = (const float*)d_in[2];  // [E,2I,H]
    const float* w2     = (const float*)d_in[3];  // [E,H,I]
    const float* w_sgu  = (const float*)d_in[4];  // [2SI,H]
    const float* w_sdn  = (const float*)d_in[5];  // [H,SI]
    float* out = (float*)d_out;

    cudaFuncSetAttribute(gemm_h<0,false>, cudaFuncAttributeMaxDynamicSharedMemorySize, SMEM_G);
    cudaFuncSetAttribute(gemm_h<0,true>,  cudaFuncAttributeMaxDynamicSharedMemorySize, SMEM_G);
    cudaFuncSetAttribute(gemm_h<1,true>,  cudaFuncAttributeMaxDynamicSharedMemorySize, SMEM_G);
    cudaFuncSetAttribute(gemm_h<2,false>, cudaFuncAttributeMaxDynamicSharedMemorySize, SMEM_G);

    __half *xh, *h, *hs;
    float *moe, *sh;
    cudaGetSymbolAddress((void**)&xh,  g_xh);
    cudaGetSymbolAddress((void**)&h,   g_h);
    cudaGetSymbolAddress((void**)&hs,  g_hs);
    cudaGetSymbolAddress((void**)&moe, g_moe);
    cudaGetSymbolAddress((void**)&sh,  g_sh);

    zero_cnt_kernel<<<1, 64>>>();
    cvt_x_kernel<<<(TN * HN / 4) / 256, 256>>>(x);
    router_kernel<<<TN, 256>>>(x, w_gate);
    offsets_kernel<<<1, 32>>>();

    // expert gate_up + silu fused: A=xh gathered, B=w13[e] interleaved, C=g_h fp16
    gemm_h<1,true><<<dim3(2 * IN / 256, 8, EN), 256, SMEM_G>>>(
        xh, w13, h, HN, HN, HN, 0, 0, (long long)2 * IN * HN, IN);

    // expert down: A=g_h compact (fp16), B=w2[e], C=g_moe scatter
    gemm_h<2,false><<<dim3(HN / 256, 8, EN), 256, SMEM_G>>>(
        h, w2, moe, IN, IN, IN, HN, 0, (long long)HN * IN, 0);

    // shared gate_up + silu fused: A=xh, B=w_sgu interleaved, C=g_hs fp16
    gemm_h<0,true><<<dim3(2 * SIN / 256, TN / 128, 1), 256, SMEM_G>>>(
        xh, w_sgu, hs, HN, HN, HN, 0, TN, 0, SIN);

    // shared down: A=g_hs (fp16), B=w_sdn, C=g_sh
    gemm_h<0,false><<<dim3(HN / 256, TN / 128, 1), 256, SMEM_G>>>(
        hs, w_sdn, sh, SIN, SIN, SIN, HN, TN, 0, 0);

    combine_kernel<<<(TN * HN / 4) / 256, 256>>>(out);
}

// round 13
// speedup vs baseline: 1.2812x; 1.2812x over previous
#include <cuda_runtime.h>
#include <cuda_fp16.h>
#include <cstdint>

// Problem constants
#define HN 2048   // hidden
#define EN 64     // experts
#define IN 1024   // expert intermediate
#define SIN 4096  // shared intermediate
#define KN 8      // top-k
#define TN 1024   // tokens

// ---------------- scratch (device globals: allocation-free) ----------------
__device__ int    g_cnt[EN];
__device__ int    g_off[EN];
__device__ int    g_list[EN * TN];        // entries: t*KN + k
__device__ float  g_topv[TN * KN];        // sigmoid routing weights
__device__ __half g_xh[TN * HN];          // fp16 copy of x
__device__ __half g_h[TN * KN * IN];      // expert hidden (fp16)   [8192, 1024]
__device__ float  g_moe[TN * KN * HN];    // expert out per pair    [8192, 2048]
__device__ __half g_hs[TN * SIN];         // shared hidden (fp16)   [1024, 4096]
__device__ float  g_sh[TN * HN];          // shared out             [1024, 2048]

// ---------------- helpers ----------------
__device__ __forceinline__ void ldm4(uint32_t r[4], uint32_t a) {
    asm volatile("ldmatrix.sync.aligned.m8n8.x4.shared.b16 {%0,%1,%2,%3}, [%4];"
                 : "=r"(r[0]), "=r"(r[1]), "=r"(r[2]), "=r"(r[3]) : "r"(a));
}

__device__ __forceinline__ void mma16816(float c[4], const uint32_t a[4],
                                         uint32_t b0, uint32_t b1) {
    asm volatile(
        "mma.sync.aligned.m16n8k16.row.col.f32.f16.f16.f32 "
        "{%0,%1,%2,%3},{%4,%5,%6,%7},{%8,%9},{%0,%1,%2,%3};"
        : "+f"(c[0]), "+f"(c[1]), "+f"(c[2]), "+f"(c[3])
        : "r"(a[0]), "r"(a[1]), "r"(a[2]), "r"(a[3]), "r"(b0), "r"(b1));
}

__device__ __forceinline__ uint32_t smem_u32(const void* p) {
    uint32_t a;
    asm("{ .reg .u64 t; cvta.to.shared.u64 t, %1; cvt.u32.u64 %0, t; }" : "=r"(a) : "l"(p));
    return a;
}

__device__ __forceinline__ void sts128(uint32_t addr, uint4 v) {
    asm volatile("st.shared.v4.b32 [%0], {%1,%2,%3,%4};"
                 :: "r"(addr), "r"(v.x), "r"(v.y), "r"(v.z), "r"(v.w) : "memory");
}

__device__ __forceinline__ float4 lds128f(uint32_t a) {
    float4 v;
    asm volatile("ld.shared.v4.f32 {%0,%1,%2,%3}, [%4];"
                 : "=f"(v.x), "=f"(v.y), "=f"(v.z), "=f"(v.w) : "r"(a));
    return v;
}

__device__ __forceinline__ void cpasync16(uint32_t dst, const void* src) {
    asm volatile("cp.async.cg.shared.global [%0], [%1], 16;" :: "r"(dst), "l"(src));
}
#define CP_COMMIT() asm volatile("cp.async.commit_group;" ::: "memory")
#define CP_WAIT1()  asm volatile("cp.async.wait_group 1;" ::: "memory")

__device__ __forceinline__ uint32_t h2u(__half2 h) { return *(uint32_t*)&h; }

__device__ __forceinline__ uint4 f8_to_h8(float4 x, float4 y) {
    return make_uint4(
        h2u(__float22half2_rn(make_float2(x.x, x.y))),
        h2u(__float22half2_rn(make_float2(x.z, x.w))),
        h2u(__float22half2_rn(make_float2(y.x, y.y))),
        h2u(__float22half2_rn(make_float2(y.z, y.w))));
}

// 64B-pitch fp16 tile (rows x 32 halves), XOR swizzle on 16B chunks:
// off(r, c) = r*64 + ((c ^ ((r>>1)&3)) * 16). Conflict-free for STS.128
// (4 threads/row mapping) and LDSM 8-lane phases (proven R4/R8).
__device__ __forceinline__ uint32_t swz(uint32_t r, uint32_t c) {
    return r * 64u + (((c ^ ((r >> 1) & 3u)) << 4));
}

// ---------------- init / convert ----------------
__global__ void zero_cnt_kernel() {
    if (threadIdx.x < EN) g_cnt[threadIdx.x] = 0;
}

__global__ void cvt_x_kernel(const float* __restrict__ x) {
    int idx = blockIdx.x * 256 + threadIdx.x;          // TN*HN/4 float4s
    float4 v = *(const float4*)&x[(size_t)idx * 4];
    uint2 o;
    o.x = h2u(__float22half2_rn(make_float2(v.x, v.y)));
    o.y = h2u(__float22half2_rn(make_float2(v.z, v.w)));
    *(uint2*)&g_xh[(size_t)idx * 4] = o;
}

// ---------------- router ----------------
__global__ void router_kernel(const float* __restrict__ x, const float* __restrict__ wg) {
    __shared__ float xs[HN];
    __shared__ float logits[EN];
    int t = blockIdx.x;
    for (int i = threadIdx.x; i < HN; i += blockDim.x) xs[i] = x[(size_t)t * HN + i];
    __syncthreads();
    int warp = threadIdx.x >> 5, lane = threadIdx.x & 31;
    for (int e = warp; e < EN; e += 8) {
        const float* w = wg + (size_t)e * HN;
        float s = 0.f;
        for (int i = lane; i < HN; i += 32) s += xs[i] * w[i];
        #pragma unroll
        for (int o = 16; o; o >>= 1) s += __shfl_xor_sync(0xffffffffu, s, o);
        if (lane == 0) logits[e] = s;
    }
    __syncthreads();
    if (threadIdx.x == 0) {
        #pragma unroll 1
        for (int k = 0; k < KN; k++) {
            int best = 0; float bv = -1e30f;
            for (int e = 0; e < EN; e++) {
                float v = logits[e];
                if (v > bv) { bv = v; best = e; }
            }
            logits[best] = -1e30f;
            g_topv[t * KN + k] = 1.f / (1.f + __expf(-bv));
            int slot = atomicAdd(&g_cnt[best], 1);
            g_list[best * TN + slot] = t * KN + k;
        }
    }
}

__global__ void offsets_kernel() {
    if (threadIdx.x == 0) {
        int s = 0;
        for (int e = 0; e < EN; e++) { g_off[e] = s; s += g_cnt[e]; }
    }
}

// ---------------- fp16 tensor-core GEMM, cp.async pipelined --------------
// C[M,N] = A[M,K] (fp16) * B[N,K]^T (f32 weights, converted in-kernel)
// MODE 0: plain rows.  MODE 1: A row = token (g_list>>3), C row compact.
// MODE 2: A row = compact, C row = g_list entry.
// GUFUSE: B rows interleaved (even=gate, odd=up); epilogue silu(g)*u -> fp16.
// CTA tile 128x256x32, 256 threads, warp grid 2x4 (warp tile 64x64).
// smem: A fp16 swz 3x8192 | Braw f32 pitch-144 2x36864 | Bcvt fp16 swz 2x16384
#define A_SLOT    8192
#define BRAW_SLOT 36864
#define BCVT_SLOT 16384
#define OFF_BRAW  (3 * A_SLOT)                  // 24576
#define OFF_BCVT  (OFF_BRAW + 2 * BRAW_SLOT)    // 98304
#define SMEM_G    (OFF_BCVT + 2 * BCVT_SLOT)    // 131072

template <int MODE, bool GUFUSE>
__global__ void __launch_bounds__(256, 1)
gemm_h(const __half* __restrict__ A, const float* __restrict__ Bw,
       void* __restrict__ Cv, int Kdim, int lda, int ldb, int ldc,
       int Mfixed, long long strideB, int hoff)
{
    extern __shared__ char smem[];
    const int tid = threadIdx.x;
    const int e  = blockIdx.z;
    const int m0 = blockIdx.y * 128;
    const int n0 = blockIdx.x * 256;

    int M = Mfixed;
    const float* Bbase = Bw;
    int off_e = 0;
    if (MODE != 0) {
        M = g_cnt[e];
        if (m0 >= M) return;
        Bbase = Bw + (size_t)e * strideB;
        off_e = g_off[e];
    }

    const uint32_t sbase = smem_u32(smem);

    // ---- A cp.async mapping: row rA = tid>>1, chunks cA, cA+1 (16B each) ----
    const int rA = tid >> 1;
    const int cA = (tid & 1) * 2;
    const __half* pA;
    {
        int gr = m0 + rA;
        int src = (gr < M) ? gr : 0;   // clamp OOB rows (discarded at epilogue)
        if (MODE == 0)      pA = A + (size_t)gr * lda;
        else if (MODE == 1) pA = A + (size_t)(g_list[e * TN + src] >> 3) * lda;
        else                pA = A + (size_t)(off_e + src) * lda;
        pA += cA * 8;
    }
    const uint32_t dA0 = swz((uint32_t)rA, (uint32_t)cA);
    const uint32_t dA1 = swz((uint32_t)rA, (uint32_t)cA + 1);

    // ---- B mapping: COALESCED: 4 threads per row, 32B segment each ----
    // rows rbase + 64j (j=0..3), segment cseg (8 f32)
    const int rbase = tid >> 2;
    const int cseg = tid & 3;
    const float* pB[4];
    uint32_t dBraw[4];     // raw-f32 ring offsets (pitch 144)
    uint32_t dBcvt[4];     // fp16 tile offsets (swz)
    #pragma unroll
    for (int j = 0; j < 4; ++j) {
        int r = rbase + j * 64;
        int jg = n0 + r;
        int brow = GUFUSE ? ((jg & 1) ? (hoff + (jg >> 1)) : (jg >> 1)) : jg;
        pB[j] = Bbase + (size_t)brow * ldb + cseg * 8;
        dBraw[j] = (uint32_t)r * 144u + (uint32_t)cseg * 32u;
        dBcvt[j] = swz((uint32_t)r, (uint32_t)cseg);
    }

    // ---- ldmatrix offsets (swz tiles) ----
    const int warp = tid >> 5, lane = tid & 31;
    const int wm = warp & 1, wn = warp >> 1;          // 2 x 4 warp grid
    const int l15 = lane & 15, chi = lane >> 4;
    uint32_t aoff[4][2], boff[4][2];
    #pragma unroll
    for (int mf = 0; mf < 4; ++mf) {
        uint32_t r = wm * 64 + mf * 16 + l15;
        #pragma unroll
        for (int ks = 0; ks < 2; ++ks) aoff[mf][ks] = swz(r, ks * 2 + chi);
    }
    #pragma unroll
    for (int np = 0; np < 4; ++np) {
        uint32_t r = wn * 64 + np * 16 + l15;
        #pragma unroll
        for (int ks = 0; ks < 2; ++ks) boff[np][ks] = swz(r, ks * 2 + chi);
    }

    float acc[4][8][4];
    #pragma unroll
    for (int mf = 0; mf < 4; mf++)
        #pragma unroll
        for (int nf = 0; nf < 8; nf++)
            #pragma unroll
            for (int r = 0; r < 4; r++) acc[mf][nf][r] = 0.f;

    const int nK = Kdim >> 5;

    auto issue_stage = [&](int s) {
        if (s < nK) {
            const int k0 = s << 5;
            uint32_t aslot = sbase + (uint32_t)(s % 3) * A_SLOT;
            cpasync16(aslot + dA0, pA + k0);
            cpasync16(aslot + dA1, pA + k0 + 8);
            uint32_t bslot = sbase + OFF_BRAW + (uint32_t)(s & 1) * BRAW_SLOT;
            #pragma unroll
            for (int j = 0; j < 4; ++j) {
                cpasync16(bslot + dBraw[j], pB[j] + k0);
                cpasync16(bslot + dBraw[j] + 16, pB[j] + k0 + 4);
            }
        }
        CP_COMMIT();
    };
    auto convert_stage = [&](int s) {
        if (s < nK) {
            uint32_t bslot = sbase + OFF_BRAW + (uint32_t)(s & 1) * BRAW_SLOT;
            uint32_t cslot = sbase + OFF_BCVT + (uint32_t)(s & 1) * BCVT_SLOT;
            #pragma unroll
            for (int j = 0; j < 4; ++j) {
                float4 lo = lds128f(bslot + dBraw[j]);
                float4 hi = lds128f(bslot + dBraw[j] + 16);
                sts128(cslot + dBcvt[j], f8_to_h8(lo, hi));
            }
        }
    };

    // prologue: stages 0,1 in flight; convert stage 0
    issue_stage(0);
    issue_stage(1);
    CP_WAIT1();          // stage 0 resident (own-thread data)
    convert_stage(0);
    __syncthreads();     // publish A stage 0 + Bcvt[0]

    for (int kt = 0; kt < nK; ++kt) {
        issue_stage(kt + 2);
        CP_WAIT1();                  // stage kt+1 resident
        convert_stage(kt + 1);       // writes Bcvt[(kt+1)&1] (own data only)
        const uint32_t abase = sbase + (uint32_t)(kt % 3) * A_SLOT;
        const uint32_t bbase = sbase + OFF_BCVT + (uint32_t)(kt & 1) * BCVT_SLOT;
        #pragma unroll
        for (int ks = 0; ks < 2; ++ks) {
            uint32_t af[4][4], bf[4][4];
            #pragma unroll
            for (int mf = 0; mf < 4; ++mf) ldm4(af[mf], abase + aoff[mf][ks]);
            #pragma unroll
            for (int np = 0; np < 4; ++np) ldm4(bf[np], bbase + boff[np][ks]);
            #pragma unroll
            for (int mf = 0; mf < 4; ++mf)
                #pragma unroll
                for (int nf = 0; nf < 8; ++nf)
                    mma16816(acc[mf][nf], af[mf],
                             bf[nf >> 1][nf & 1], bf[nf >> 1][(nf & 1) | 2]);
        }
        __syncthreads();             // publish next stage; guard slot reuse
    }

    // ---- epilogue ----
    #pragma unroll
    for (int mf = 0; mf < 4; ++mf) {
        #pragma unroll
        for (int half = 0; half < 2; ++half) {
            int rl = wm * 64 + mf * 16 + (lane >> 2) + half * 8;
            int gr = m0 + rl;
            if (gr >= M) continue;
            size_t crow;
            if (MODE == 0)      crow = (size_t)gr;
            else if (MODE == 1) crow = (size_t)(off_e + gr);
            else                crow = (size_t)g_list[e * TN + gr];
            if (GUFUSE) {
                __half* hp = (__half*)Cv + crow * (size_t)hoff
                           + ((n0 + wn * 64) >> 1) + (lane & 3);
                #pragma unroll
                for (int nf = 0; nf < 8; ++nf) {
                    float g = acc[mf][nf][half * 2];
                    float u = acc[mf][nf][half * 2 + 1];
                    float h = g / (1.f + __expf(-g)) * u;
                    hp[nf * 4] = __float2half_rn(h);
                }
            } else {
                float* cp = (float*)Cv + crow * (size_t)ldc + n0 + wn * 64 + (lane & 3) * 2;
                #pragma unroll
                for (int nf = 0; nf < 8; ++nf) {
                    float2 v = make_float2(acc[mf][nf][half * 2], acc[mf][nf][half * 2 + 1]);
                    *(float2*)(cp + nf * 8) = v;
                }
            }
        }
    }
}

// ---------------- combine ----------------
__global__ void combine_kernel(float* __restrict__ out) {
    int idx = blockIdx.x * 256 + threadIdx.x;          // over [1024 * 512] float4
    int t = idx >> 9, d = (idx & 511) * 4;
    float4 acc = make_float4(0.f, 0.f, 0.f, 0.f);
    #pragma unroll
    for (int k = 0; k < KN; k++) {
        float w = g_topv[t * KN + k];
        float4 m = *(const float4*)&g_moe[(size_t)(t * KN + k) * HN + d];
        acc.x += w * m.x; acc.y += w * m.y; acc.z += w * m.z; acc.w += w * m.w;
    }
    float4 s = *(const float4*)&g_sh[(size_t)t * HN + d];
    const float inv = 1.f / (float)(KN + 1);
    float4 o;
    o.x = (s.x + KN * acc.x) * inv;
    o.y = (s.y + KN * acc.y) * inv;
    o.z = (s.z + KN * acc.z) * inv;
    o.w = (s.w + KN * acc.w) * inv;
    *(float4*)&out[(size_t)t * HN + d] = o;
}

// ---------------- launch ----------------
extern "C" void kernel_launch(void* const* d_in, const int* in_sizes, int n_in,
                              void* d_out, int out_size)
{
    const float* x      = (const float*)d_in[0];  // [T,H]
    const float* w_gate = (const float*)d_in[1];  // [E,H]
    const float* w13    = (const float*)d_in[2];  // [E,2I,H]
    const float* w2     = (const float*)d_in[3];  // [E,H,I]
    const float* w_sgu  = (const float*)d_in[4];  // [2SI,H]
    const float* w_sdn  = (const float*)d_in[5];  // [H,SI]
    float* out = (float*)d_out;

    cudaFuncSetAttribute(gemm_h<0,false>, cudaFuncAttributeMaxDynamicSharedMemorySize, SMEM_G);
    cudaFuncSetAttribute(gemm_h<0,true>,  cudaFuncAttributeMaxDynamicSharedMemorySize, SMEM_G);
    cudaFuncSetAttribute(gemm_h<1,true>,  cudaFuncAttributeMaxDynamicSharedMemorySize, SMEM_G);
    cudaFuncSetAttribute(gemm_h<2,false>, cudaFuncAttributeMaxDynamicSharedMemorySize, SMEM_G);

    __half *xh, *h, *hs;
    float *moe, *sh;
    cudaGetSymbolAddress((void**)&xh,  g_xh);
    cudaGetSymbolAddress((void**)&h,   g_h);
    cudaGetSymbolAddress((void**)&hs,  g_hs);
    cudaGetSymbolAddress((void**)&moe, g_moe);
    cudaGetSymbolAddress((void**)&sh,  g_sh);

    zero_cnt_kernel<<<1, 64>>>();
    cvt_x_kernel<<<(TN * HN / 4) / 256, 256>>>(x);
    router_kernel<<<TN, 256>>>(x, w_gate);
    offsets_kernel<<<1, 32>>>();

    // expert gate_up + silu fused: A=xh gathered, B=w13[e] interleaved, C=g_h fp16
    gemm_h<1,true><<<dim3(2 * IN / 256, 8, EN), 256, SMEM_G>>>(
        xh, w13, h, HN, HN, HN, 0, 0, (long long)2 * IN * HN, IN);

    // expert down: A=g_h compact (fp16), B=w2[e], C=g_moe scatter
    gemm_h<2,false><<<dim3(HN / 256, 8, EN), 256, SMEM_G>>>(
        h, w2, moe, IN, IN, IN, HN, 0, (long long)HN * IN, 0);

    // shared gate_up + silu fused: A=xh, B=w_sgu interleaved, C=g_hs fp16
    gemm_h<0,true><<<dim3(2 * SIN / 256, TN / 128, 1), 256, SMEM_G>>>(
        xh, w_sgu, hs, HN, HN, HN, 0, TN, 0, SIN);

    // shared down: A=g_hs (fp16), B=w_sdn, C=g_sh
    gemm_h<0,false><<<dim3(HN / 256, TN / 128, 1), 256, SMEM_G>>>(
        hs, w_sdn, sh, SIN, SIN, SIN, HN, TN, 0, 0);

    combine_kernel<<<(TN * HN / 4) / 256, 256>>>(out);
}

// round 14
// speedup vs baseline: 1.2813x; 1.0001x over previous
#include <cuda_runtime.h>
#include <cuda_fp16.h>
#include <cstdint>

// Problem constants
#define HN 2048   // hidden
#define EN 64     // experts
#define IN 1024   // expert intermediate
#define SIN 4096  // shared intermediate
#define KN 8      // top-k
#define TN 1024   // tokens

// ---------------- scratch (device globals: allocation-free) ----------------
__device__ int    g_cnt[EN];
__device__ int    g_off[EN];
__device__ int    g_list[EN * TN];        // entries: t*KN + k
__device__ float  g_topv[TN * KN];        // sigmoid routing weights
__device__ __half g_xh[TN * HN];          // fp16 copy of x
__device__ __half g_h[TN * KN * IN];      // expert hidden (fp16)   [8192, 1024]
__device__ float  g_moe[TN * KN * HN];    // expert out per pair    [8192, 2048]
__device__ __half g_hs[TN * SIN];         // shared hidden (fp16)   [1024, 4096]
__device__ float  g_sh[TN * HN];          // shared out             [1024, 2048]

// ---------------- helpers ----------------
__device__ __forceinline__ void ldm4(uint32_t r[4], uint32_t a) {
    asm volatile("ldmatrix.sync.aligned.m8n8.x4.shared.b16 {%0,%1,%2,%3}, [%4];"
                 : "=r"(r[0]), "=r"(r[1]), "=r"(r[2]), "=r"(r[3]) : "r"(a));
}

__device__ __forceinline__ void mma16816(float c[4], const uint32_t a[4],
                                         uint32_t b0, uint32_t b1) {
    asm volatile(
        "mma.sync.aligned.m16n8k16.row.col.f32.f16.f16.f32 "
        "{%0,%1,%2,%3},{%4,%5,%6,%7},{%8,%9},{%0,%1,%2,%3};"
        : "+f"(c[0]), "+f"(c[1]), "+f"(c[2]), "+f"(c[3])
        : "r"(a[0]), "r"(a[1]), "r"(a[2]), "r"(a[3]), "r"(b0), "r"(b1));
}

__device__ __forceinline__ uint32_t smem_u32(const void* p) {
    uint32_t a;
    asm("{ .reg .u64 t; cvta.to.shared.u64 t, %1; cvt.u32.u64 %0, t; }" : "=r"(a) : "l"(p));
    return a;
}

__device__ __forceinline__ void sts128(uint32_t addr, uint4 v) {
    asm volatile("st.shared.v4.b32 [%0], {%1,%2,%3,%4};"
                 :: "r"(addr), "r"(v.x), "r"(v.y), "r"(v.z), "r"(v.w) : "memory");
}

__device__ __forceinline__ float4 lds128f(uint32_t a) {
    float4 v;
    asm volatile("ld.shared.v4.f32 {%0,%1,%2,%3}, [%4];"
                 : "=f"(v.x), "=f"(v.y), "=f"(v.z), "=f"(v.w) : "r"(a));
    return v;
}

__device__ __forceinline__ void cpasync16(uint32_t dst, const void* src) {
    asm volatile("cp.async.cg.shared.global [%0], [%1], 16;" :: "r"(dst), "l"(src));
}
#define CP_COMMIT() asm volatile("cp.async.commit_group;" ::: "memory")
#define CP_WAIT1()  asm volatile("cp.async.wait_group 1;" ::: "memory")

__device__ __forceinline__ uint32_t h2u(__half2 h) { return *(uint32_t*)&h; }

__device__ __forceinline__ uint4 f8_to_h8(float4 x, float4 y) {
    return make_uint4(
        h2u(__float22half2_rn(make_float2(x.x, x.y))),
        h2u(__float22half2_rn(make_float2(x.z, x.w))),
        h2u(__float22half2_rn(make_float2(y.x, y.y))),
        h2u(__float22half2_rn(make_float2(y.z, y.w))));
}

// 64B-pitch fp16 tile (rows x 32 halves), XOR swizzle on 16B chunks:
// off(r, c) = r*64 + ((c ^ ((r>>1)&3)) * 16). Conflict-free for STS.128
// (4 threads/row mapping) and LDSM 8-lane phases (proven R4/R8).
__device__ __forceinline__ uint32_t swz(uint32_t r, uint32_t c) {
    return r * 64u + (((c ^ ((r >> 1) & 3u)) << 4));
}

// ---------------- init / convert ----------------
__global__ void zero_cnt_kernel() {
    if (threadIdx.x < EN) g_cnt[threadIdx.x] = 0;
}

__global__ void cvt_x_kernel(const float* __restrict__ x) {
    int idx = blockIdx.x * 256 + threadIdx.x;          // TN*HN/4 float4s
    float4 v = *(const float4*)&x[(size_t)idx * 4];
    uint2 o;
    o.x = h2u(__float22half2_rn(make_float2(v.x, v.y)));
    o.y = h2u(__float22half2_rn(make_float2(v.z, v.w)));
    *(uint2*)&g_xh[(size_t)idx * 4] = o;
}

// ---------------- router ----------------
__global__ void router_kernel(const float* __restrict__ x, const float* __restrict__ wg) {
    __shared__ float xs[HN];
    __shared__ float logits[EN];
    int t = blockIdx.x;
    for (int i = threadIdx.x; i < HN; i += blockDim.x) xs[i] = x[(size_t)t * HN + i];
    __syncthreads();
    int warp = threadIdx.x >> 5, lane = threadIdx.x & 31;
    for (int e = warp; e < EN; e += 8) {
        const float* w = wg + (size_t)e * HN;
        float s = 0.f;
        for (int i = lane; i < HN; i += 32) s += xs[i] * w[i];
        #pragma unroll
        for (int o = 16; o; o >>= 1) s += __shfl_xor_sync(0xffffffffu, s, o);
        if (lane == 0) logits[e] = s;
    }
    __syncthreads();
    if (threadIdx.x == 0) {
        #pragma unroll 1
        for (int k = 0; k < KN; k++) {
            int best = 0; float bv = -1e30f;
            for (int e = 0; e < EN; e++) {
                float v = logits[e];
                if (v > bv) { bv = v; best = e; }
            }
            logits[best] = -1e30f;
            g_topv[t * KN + k] = 1.f / (1.f + __expf(-bv));
            int slot = atomicAdd(&g_cnt[best], 1);
            g_list[best * TN + slot] = t * KN + k;
        }
    }
}

__global__ void offsets_kernel() {
    if (threadIdx.x == 0) {
        int s = 0;
        for (int e = 0; e < EN; e++) { g_off[e] = s; s += g_cnt[e]; }
    }
}

// ---------------- fp16 tensor-core GEMM, cp.async pipelined --------------
// C[M,N] = A[M,K] (fp16) * B[N,K]^T (f32 weights, converted in-kernel)
// MODE 0: plain rows.  MODE 1: A row = token (g_list>>3), C row compact.
// MODE 2: A row = compact, C row = g_list entry.
// GUFUSE: B rows interleaved (even=gate, odd=up); epilogue silu(g)*u -> fp16.
// CTA tile 128x256x32, 256 threads, warp grid 2x4 (warp tile 64x64).
// smem: A fp16 swz 3x8192 | Braw f32 pitch-144 2x36864 | Bcvt fp16 swz 2x16384
#define A_SLOT    8192
#define BRAW_SLOT 36864
#define BCVT_SLOT 16384
#define OFF_BRAW  (3 * A_SLOT)                  // 24576
#define OFF_BCVT  (OFF_BRAW + 2 * BRAW_SLOT)    // 98304
#define SMEM_G    (OFF_BCVT + 2 * BCVT_SLOT)    // 131072

template <int MODE, bool GUFUSE>
__global__ void __launch_bounds__(256, 1)
gemm_h(const __half* __restrict__ A, const float* __restrict__ Bw,
       void* __restrict__ Cv, int Kdim, int lda, int ldb, int ldc,
       int Mfixed, long long strideB, int hoff)
{
    extern __shared__ char smem[];
    const int tid = threadIdx.x;
    const int e  = blockIdx.z;
    const int m0 = blockIdx.y * 128;
    const int n0 = blockIdx.x * 256;

    int M = Mfixed;
    const float* Bbase = Bw;
    int off_e = 0;
    if (MODE != 0) {
        M = g_cnt[e];
        if (m0 >= M) return;
        Bbase = Bw + (size_t)e * strideB;
        off_e = g_off[e];
    }

    const uint32_t sbase = smem_u32(smem);

    // ---- A cp.async mapping: row rA = tid>>1, chunks cA, cA+1 (16B each) ----
    const int rA = tid >> 1;
    const int cA = (tid & 1) * 2;
    const __half* pA;
    {
        int gr = m0 + rA;
        int src = (gr < M) ? gr : 0;   // clamp OOB rows (discarded at epilogue)
        if (MODE == 0)      pA = A + (size_t)gr * lda;
        else if (MODE == 1) pA = A + (size_t)(g_list[e * TN + src] >> 3) * lda;
        else                pA = A + (size_t)(off_e + src) * lda;
        pA += cA * 8;
    }
    const uint32_t dA0 = swz((uint32_t)rA, (uint32_t)cA);
    const uint32_t dA1 = swz((uint32_t)rA, (uint32_t)cA + 1);

    // ---- B mapping: COALESCED: 4 threads per row, 32B segment each ----
    // rows rbase + 64j (j=0..3), segment cseg (8 f32)
    const int rbase = tid >> 2;
    const int cseg = tid & 3;
    const float* pB[4];
    uint32_t dBraw[4];     // raw-f32 ring offsets (pitch 144)
    uint32_t dBcvt[4];     // fp16 tile offsets (swz)
    #pragma unroll
    for (int j = 0; j < 4; ++j) {
        int r = rbase + j * 64;
        int jg = n0 + r;
        int brow = GUFUSE ? ((jg & 1) ? (hoff + (jg >> 1)) : (jg >> 1)) : jg;
        pB[j] = Bbase + (size_t)brow * ldb + cseg * 8;
        dBraw[j] = (uint32_t)r * 144u + (uint32_t)cseg * 32u;
        dBcvt[j] = swz((uint32_t)r, (uint32_t)cseg);
    }

    // ---- ldmatrix offsets (swz tiles) ----
    const int warp = tid >> 5, lane = tid & 31;
    const int wm = warp & 1, wn = warp >> 1;          // 2 x 4 warp grid
    const int l15 = lane & 15, chi = lane >> 4;
    uint32_t aoff[4][2], boff[4][2];
    #pragma unroll
    for (int mf = 0; mf < 4; ++mf) {
        uint32_t r = wm * 64 + mf * 16 + l15;
        #pragma unroll
        for (int ks = 0; ks < 2; ++ks) aoff[mf][ks] = swz(r, ks * 2 + chi);
    }
    #pragma unroll
    for (int np = 0; np < 4; ++np) {
        uint32_t r = wn * 64 + np * 16 + l15;
        #pragma unroll
        for (int ks = 0; ks < 2; ++ks) boff[np][ks] = swz(r, ks * 2 + chi);
    }

    float acc[4][8][4];
    #pragma unroll
    for (int mf = 0; mf < 4; mf++)
        #pragma unroll
        for (int nf = 0; nf < 8; nf++)
            #pragma unroll
            for (int r = 0; r < 4; r++) acc[mf][nf][r] = 0.f;

    const int nK = Kdim >> 5;

    auto issue_stage = [&](int s) {
        if (s < nK) {
            const int k0 = s << 5;
            uint32_t aslot = sbase + (uint32_t)(s % 3) * A_SLOT;
            cpasync16(aslot + dA0, pA + k0);
            cpasync16(aslot + dA1, pA + k0 + 8);
            uint32_t bslot = sbase + OFF_BRAW + (uint32_t)(s & 1) * BRAW_SLOT;
            #pragma unroll
            for (int j = 0; j < 4; ++j) {
                cpasync16(bslot + dBraw[j], pB[j] + k0);
                cpasync16(bslot + dBraw[j] + 16, pB[j] + k0 + 4);
            }
        }
        CP_COMMIT();
    };
    auto convert_stage = [&](int s) {
        if (s < nK) {
            uint32_t bslot = sbase + OFF_BRAW + (uint32_t)(s & 1) * BRAW_SLOT;
            uint32_t cslot = sbase + OFF_BCVT + (uint32_t)(s & 1) * BCVT_SLOT;
            #pragma unroll
            for (int j = 0; j < 4; ++j) {
                float4 lo = lds128f(bslot + dBraw[j]);
                float4 hi = lds128f(bslot + dBraw[j] + 16);
                sts128(cslot + dBcvt[j], f8_to_h8(lo, hi));
            }
        }
    };

    // prologue: stages 0,1 in flight; convert stage 0
    issue_stage(0);
    issue_stage(1);
    CP_WAIT1();          // stage 0 resident (own-thread data)
    convert_stage(0);
    __syncthreads();     // publish A stage 0 + Bcvt[0]

    for (int kt = 0; kt < nK; ++kt) {
        issue_stage(kt + 2);
        CP_WAIT1();                  // stage kt+1 resident
        convert_stage(kt + 1);       // writes Bcvt[(kt+1)&1] (own data only)
        const uint32_t abase = sbase + (uint32_t)(kt % 3) * A_SLOT;
        const uint32_t bbase = sbase + OFF_BCVT + (uint32_t)(kt & 1) * BCVT_SLOT;
        #pragma unroll
        for (int ks = 0; ks < 2; ++ks) {
            uint32_t af[4][4], bf[4][4];
            #pragma unroll
            for (int mf = 0; mf < 4; ++mf) ldm4(af[mf], abase + aoff[mf][ks]);
            #pragma unroll
            for (int np = 0; np < 4; ++np) ldm4(bf[np], bbase + boff[np][ks]);
            #pragma unroll
            for (int mf = 0; mf < 4; ++mf)
                #pragma unroll
                for (int nf = 0; nf < 8; ++nf)
                    mma16816(acc[mf][nf], af[mf],
                             bf[nf >> 1][nf & 1], bf[nf >> 1][(nf & 1) | 2]);
        }
        __syncthreads();             // publish next stage; guard slot reuse
    }

    // ---- epilogue ----
    #pragma unroll
    for (int mf = 0; mf < 4; ++mf) {
        #pragma unroll
        for (int half = 0; half < 2; ++half) {
            int rl = wm * 64 + mf * 16 + (lane >> 2) + half * 8;
            int gr = m0 + rl;
            if (gr >= M) continue;
            size_t crow;
            if (MODE == 0)      crow = (size_t)gr;
            else if (MODE == 1) crow = (size_t)(off_e + gr);
            else                crow = (size_t)g_list[e * TN + gr];
            if (GUFUSE) {
                __half* hp = (__half*)Cv + crow * (size_t)hoff
                           + ((n0 + wn * 64) >> 1) + (lane & 3);
                #pragma unroll
                for (int nf = 0; nf < 8; ++nf) {
                    float g = acc[mf][nf][half * 2];
                    float u = acc[mf][nf][half * 2 + 1];
                    float h = g / (1.f + __expf(-g)) * u;
                    hp[nf * 4] = __float2half_rn(h);
                }
            } else {
                float* cp = (float*)Cv + crow * (size_t)ldc + n0 + wn * 64 + (lane & 3) * 2;
                #pragma unroll
                for (int nf = 0; nf < 8; ++nf) {
                    float2 v = make_float2(acc[mf][nf][half * 2], acc[mf][nf][half * 2 + 1]);
                    *(float2*)(cp + nf * 8) = v;
                }
            }
        }
    }
}

// ---------------- combine ----------------
__global__ void combine_kernel(float* __restrict__ out) {
    int idx = blockIdx.x * 256 + threadIdx.x;          // over [1024 * 512] float4
    int t = idx >> 9, d = (idx & 511) * 4;
    float4 acc = make_float4(0.f, 0.f, 0.f, 0.f);
    #pragma unroll
    for (int k = 0; k < KN; k++) {
        float w = g_topv[t * KN + k];
        float4 m = *(const float4*)&g_moe[(size_t)(t * KN + k) * HN + d];
        acc.x += w * m.x; acc.y += w * m.y; acc.z += w * m.z; acc.w += w * m.w;
    }
    float4 s = *(const float4*)&g_sh[(size_t)t * HN + d];
    const float inv = 1.f / (float)(KN + 1);
    float4 o;
    o.x = (s.x + KN * acc.x) * inv;
    o.y = (s.y + KN * acc.y) * inv;
    o.z = (s.z + KN * acc.z) * inv;
    o.w = (s.w + KN * acc.w) * inv;
    *(float4*)&out[(size_t)t * HN + d] = o;
}

// ---------------- launch ----------------
extern "C" void kernel_launch(void* const* d_in, const int* in_sizes, int n_in,
                              void* d_out, int out_size)
{
    const float* x      = (const float*)d_in[0];  // [T,H]
    const float* w_gate = (const float*)d_in[1];  // [E,H]
    const float* w13    = (const float*)d_in[2];  // [E,2I,H]
    const float* w2     = (const float*)d_in[3];  // [E,H,I]
    const float* w_sgu  = (const float*)d_in[4];  // [2SI,H]
    const float* w_sdn  = (const float*)d_in[5];  // [H,SI]
    float* out = (float*)d_out;

    cudaFuncSetAttribute(gemm_h<0,false>, cudaFuncAttributeMaxDynamicSharedMemorySize, SMEM_G);
    cudaFuncSetAttribute(gemm_h<0,true>,  cudaFuncAttributeMaxDynamicSharedMemorySize, SMEM_G);
    cudaFuncSetAttribute(gemm_h<1,true>,  cudaFuncAttributeMaxDynamicSharedMemorySize, SMEM_G);
    cudaFuncSetAttribute(gemm_h<2,false>, cudaFuncAttributeMaxDynamicSharedMemorySize, SMEM_G);

    __half *xh, *h, *hs;
    float *moe, *sh;
    cudaGetSymbolAddress((void**)&xh,  g_xh);
    cudaGetSymbolAddress((void**)&h,   g_h);
    cudaGetSymbolAddress((void**)&hs,  g_hs);
    cudaGetSymbolAddress((void**)&moe, g_moe);
    cudaGetSymbolAddress((void**)&sh,  g_sh);

    zero_cnt_kernel<<<1, 64>>>();
    cvt_x_kernel<<<(TN * HN / 4) / 256, 256>>>(x);
    router_kernel<<<TN, 256>>>(x, w_gate);
    offsets_kernel<<<1, 32>>>();

    // expert gate_up + silu fused: A=xh gathered, B=w13[e] interleaved, C=g_h fp16
    gemm_h<1,true><<<dim3(2 * IN / 256, 8, EN), 256, SMEM_G>>>(
        xh, w13, h, HN, HN, HN, 0, 0, (long long)2 * IN * HN, IN);

    // expert down: A=g_h compact (fp16), B=w2[e], C=g_moe scatter
    gemm_h<2,false><<<dim3(HN / 256, 8, EN), 256, SMEM_G>>>(
        h, w2, moe, IN, IN, IN, HN, 0, (long long)HN * IN, 0);

    // shared gate_up + silu fused: A=xh, B=w_sgu interleaved, C=g_hs fp16
    gemm_h<0,true><<<dim3(2 * SIN / 256, TN / 128, 1), 256, SMEM_G>>>(
        xh, w_sgu, hs, HN, HN, HN, 0, TN, 0, SIN);

    // shared down: A=g_hs (fp16), B=w_sdn, C=g_sh
    gemm_h<0,false><<<dim3(HN / 256, TN / 128, 1), 256, SMEM_G>>>(
        hs, w_sdn, sh, SIN, SIN, SIN, HN, TN, 0, 0);

    combine_kernel<<<(TN * HN / 4) / 256, 256>>>(out);
}